// round 10
// baseline (speedup 1.0000x reference)
#include <cuda_runtime.h>
#include <cuda_fp16.h>
#include <cstdint>

#define D_FEAT      64
#define N_NODES_MAX 100000
#define GSZ         8             // threads per edge-group (8 feats per thread)
#define EPS         64            // edges per group
#define SUBS        16            // groups per block (128 threads / 8)
#define EPB         (EPS * SUBS)  // 1024 edges per block
#define THREADS     128

// Scratch (allocation-free). Intermediate hop in fp16.
__device__ __half g_tmp[(size_t)N_NODES_MAX * D_FEAT];

__device__ __forceinline__ void red_add_v4(float* p, float4 a) {
    asm volatile("red.global.add.v4.f32 [%0], {%1, %2, %3, %4};"
                 :: "l"(p), "f"(a.x), "f"(a.y), "f"(a.z), "f"(a.w)
                 : "memory");
}
__device__ __forceinline__ void red_add_h2(uint32_t* p, float2 v) {
    __half2 h = __float22half2_rn(v);
    asm volatile("red.global.add.noftz.f16x2 [%0], %1;"
                 :: "l"(p), "r"(*reinterpret_cast<uint32_t*>(&h))
                 : "memory");
}

// ---- 8-feature (per-thread) row helpers ----
template <bool HALF>
__device__ __forceinline__ void ld_feat8(const char* p, float4& lo, float4& hi) {
    if (HALF) {
        uint4 u = *reinterpret_cast<const uint4*>(p);      // 8 halves, 1 LDG.128
        float2 a = __half22float2(*reinterpret_cast<__half2*>(&u.x));
        float2 b = __half22float2(*reinterpret_cast<__half2*>(&u.y));
        float2 c = __half22float2(*reinterpret_cast<__half2*>(&u.z));
        float2 d = __half22float2(*reinterpret_cast<__half2*>(&u.w));
        lo = make_float4(a.x, a.y, b.x, b.y);
        hi = make_float4(c.x, c.y, d.x, d.y);
    } else {
        lo = *reinterpret_cast<const float4*>(p);          // 2 LDG.128
        hi = *reinterpret_cast<const float4*>(p + 16);
    }
}
template <bool HALF>
__device__ __forceinline__ void st_feat8(char* p, float4 lo, float4 hi) {
    if (HALF) {
        uint4 u;
        __half2 h0 = __float22half2_rn(make_float2(lo.x, lo.y));
        __half2 h1 = __float22half2_rn(make_float2(lo.z, lo.w));
        __half2 h2 = __float22half2_rn(make_float2(hi.x, hi.y));
        __half2 h3 = __float22half2_rn(make_float2(hi.z, hi.w));
        u.x = *reinterpret_cast<uint32_t*>(&h0);
        u.y = *reinterpret_cast<uint32_t*>(&h1);
        u.z = *reinterpret_cast<uint32_t*>(&h2);
        u.w = *reinterpret_cast<uint32_t*>(&h3);
        *reinterpret_cast<uint4*>(p) = u;
    } else {
        *reinterpret_cast<float4*>(p)      = lo;
        *reinterpret_cast<float4*>(p + 16) = hi;
    }
}
template <bool HALF>
__device__ __forceinline__ void red_feat8(char* p, float4 lo, float4 hi) {
    if (HALF) {
        uint32_t* u = reinterpret_cast<uint32_t*>(p);
        red_add_h2(u + 0, make_float2(lo.x, lo.y));
        red_add_h2(u + 1, make_float2(lo.z, lo.w));
        red_add_h2(u + 2, make_float2(hi.x, hi.y));
        red_add_h2(u + 3, make_float2(hi.z, hi.w));
    } else {
        red_add_v4(reinterpret_cast<float*>(p),      lo);
        red_add_v4(reinterpret_cast<float*>(p + 16), hi);
    }
}

// Sorted-row SpMM, 8-thread groups (4 groups per warp -> ~2x fewer warp-inst
// per edge than 16-thread groups). Interior runs -> exclusive STG, boundary
// runs -> red.add into pre-zeroed dst. 4 edges batched per iteration.
template <bool SRC_H, bool DST_H>
__global__ void __launch_bounds__(THREADS)
spmm_kernel(const char* __restrict__ src,
            const int*  __restrict__ erow,
            const int*  __restrict__ ecol,
            const float* __restrict__ eval,
            char*       __restrict__ dst,
            int n_edges) {
    constexpr int SRC_RB = SRC_H ? 128 : 256;   // bytes per feature row
    constexpr int DST_RB = DST_H ? 128 : 256;
    constexpr int SRC_TB = SRC_H ? 16 : 32;     // bytes per thread (8 feats)
    constexpr int DST_TB = DST_H ? 16 : 32;

    __shared__ alignas(16) int   s_row[EPB];
    __shared__ alignas(16) int   s_off[EPB];    // col * SRC_RB
    __shared__ alignas(16) float s_val[EPB];

    const int base = blockIdx.x * EPB;
    const int tid  = threadIdx.x;

    // Vectorized staging (2 int4 per thread per array); pad w/ last row, val=0.
    #pragma unroll
    for (int i = tid * 4; i < EPB; i += THREADS * 4) {
        const int e = base + i;
        if (e + 3 < n_edges) {
            int4   r = *reinterpret_cast<const int4*>(erow + e);
            int4   c = *reinterpret_cast<const int4*>(ecol + e);
            float4 v = *reinterpret_cast<const float4*>(eval + e);
            c.x *= SRC_RB; c.y *= SRC_RB; c.z *= SRC_RB; c.w *= SRC_RB;
            *reinterpret_cast<int4*>(s_row + i)   = r;
            *reinterpret_cast<int4*>(s_off + i)   = c;
            *reinterpret_cast<float4*>(s_val + i) = v;
        } else {
            #pragma unroll
            for (int k = 0; k < 4; k++) {
                int ee   = e + k;
                int esrc = min(ee, n_edges - 1);
                int in   = (ee < n_edges);
                s_row[i + k] = erow[esrc];
                s_off[i + k] = in ? ecol[esrc] * SRC_RB : 0;
                s_val[i + k] = in ? eval[esrc] : 0.f;
            }
        }
    }
    __syncthreads();

    const int d8  = tid & (GSZ - 1);            // feature octet within the row
    const int sub = tid / GSZ;
    const int off = sub * EPS;
    const char* sp = src + d8 * SRC_TB;
    char*       dp = dst + d8 * DST_TB;

    int    cur       = s_row[off];
    int    run_start = 0;
    float4 alo = make_float4(0.f, 0.f, 0.f, 0.f);
    float4 ahi = make_float4(0.f, 0.f, 0.f, 0.f);

    for (int ib = 0; ib < EPS; ib += 4) {
        const int4   r4 = *reinterpret_cast<const int4*>(s_row + off + ib);
        const int4   c4 = *reinterpret_cast<const int4*>(s_off + off + ib);
        const float4 v4 = *reinterpret_cast<const float4*>(s_val + off + ib);

        // 4 edges' gathers in flight
        float4 g0l, g0h, g1l, g1h, g2l, g2h, g3l, g3h;
        ld_feat8<SRC_H>(sp + c4.x, g0l, g0h);
        ld_feat8<SRC_H>(sp + c4.y, g1l, g1h);
        ld_feat8<SRC_H>(sp + c4.z, g2l, g2h);
        ld_feat8<SRC_H>(sp + c4.w, g3l, g3h);

        #define STEP(R, V, GL, GH, IDX)                                      \
        do {                                                                 \
            if ((R) != cur) {                                                \
                char* p = dp + (size_t)cur * DST_RB;                         \
                if (run_start > 0) {                                         \
                    st_feat8<DST_H>(p, alo, ahi);   /* exclusive interior */ \
                } else {                                                     \
                    red_feat8<DST_H>(p, alo, ahi);  /* boundary */           \
                }                                                            \
                alo = make_float4(0.f, 0.f, 0.f, 0.f);                       \
                ahi = make_float4(0.f, 0.f, 0.f, 0.f);                       \
                cur = (R);                                                   \
                run_start = (IDX);                                           \
            }                                                                \
            alo.x += (V) * (GL).x;  alo.y += (V) * (GL).y;                   \
            alo.z += (V) * (GL).z;  alo.w += (V) * (GL).w;                   \
            ahi.x += (V) * (GH).x;  ahi.y += (V) * (GH).y;                   \
            ahi.z += (V) * (GH).z;  ahi.w += (V) * (GH).w;                   \
        } while (0)

        STEP(r4.x, v4.x, g0l, g0h, ib + 0);
        STEP(r4.y, v4.y, g1l, g1h, ib + 1);
        STEP(r4.z, v4.z, g2l, g2h, ib + 2);
        STEP(r4.w, v4.w, g3l, g3h, ib + 3);
        #undef STEP
    }

    // Final run may continue into the next group -> always atomic.
    red_feat8<DST_H>(dp + (size_t)cur * DST_RB, alo, ahi);
}

extern "C" void kernel_launch(void* const* d_in, const int* in_sizes, int n_in,
                              void* d_out, int out_size) {
    const char*  x    = (const char*) d_in[0];
    const int*   erow = (const int*)  d_in[1];
    const int*   ecol = (const int*)  d_in[2];
    const float* eval = (const float*)d_in[3];
    char*        out  = (char*)d_out;

    const int n_edges = in_sizes[1];
    const int n_rows  = out_size / D_FEAT;
    const int n_elems = n_rows * D_FEAT;

    void* tmp_sym = nullptr;
    cudaGetSymbolAddress(&tmp_sym, g_tmp);
    char* tmp = (char*)tmp_sym;

    const int sgrid = (n_edges + EPB - 1) / EPB;

    // Host-side resources for the fork/join (no device memory involved).
    static cudaStream_t side = nullptr;
    static cudaEvent_t  ev_fork = nullptr, ev_join = nullptr;
    if (!side) {
        cudaStreamCreateWithFlags(&side, cudaStreamNonBlocking);
        cudaEventCreateWithFlags(&ev_fork, cudaEventDisableTiming);
        cudaEventCreateWithFlags(&ev_join, cudaEventDisableTiming);
    }

    // Critical path: zero tmp (needed by hop 1's boundary red.adds).
    cudaMemsetAsync(tmp, 0, (size_t)n_elems * 2);

    // Fork: zero out on the side stream, overlapping hop 1.
    cudaEventRecord(ev_fork, 0);
    cudaStreamWaitEvent(side, ev_fork, 0);
    cudaMemsetAsync(out, 0, (size_t)n_elems * 4, side);
    cudaEventRecord(ev_join, side);

    // Hop 1: tmp(fp16) = A @ x(fp32)   (overlaps memset(out))
    spmm_kernel<false, true><<<sgrid, THREADS>>>(x, erow, ecol, eval, tmp, n_edges);

    // Join: out must be zeroed before hop 2's red.adds.
    cudaStreamWaitEvent(0, ev_join, 0);

    // Hop 2: out(fp32) = A @ tmp(fp16)
    spmm_kernel<true, false><<<sgrid, THREADS>>>(tmp, erow, ecol, eval, out, n_edges);
}

// round 11
// speedup vs baseline: 1.2970x; 1.2970x over previous
#include <cuda_runtime.h>
#include <cuda_fp16.h>
#include <cstdint>

#define D_FEAT      64
#define N_NODES_MAX 100000
#define EPS         64            // edges per 16-thread group (R9-proven)
#define SUBS        8             // groups per block
#define EPB         (EPS * SUBS)  // 512 edges per block
#define THREADS     128

// Scratch (allocation-free). Intermediate hop in fp16.
__device__ __half g_tmp[(size_t)N_NODES_MAX * D_FEAT];

// ---- packed f32x2 helpers (FFMA2 on sm_103a; PTX-only path) ----
__device__ __forceinline__ uint64_t pack2(float lo, float hi) {
    uint64_t r;
    asm("mov.b64 %0, {%1, %2};" : "=l"(r) : "f"(lo), "f"(hi));
    return r;
}
__device__ __forceinline__ float2 unpack2(uint64_t v) {
    float2 r;
    asm("mov.b64 {%0, %1}, %2;" : "=f"(r.x), "=f"(r.y) : "l"(v));
    return r;
}
__device__ __forceinline__ void fma2(uint64_t& acc, uint64_t a, uint64_t b) {
    asm("fma.rn.f32x2 %0, %1, %2, %3;" : "=l"(acc) : "l"(a), "l"(b), "l"(acc));
}

__device__ __forceinline__ void red_add_v4(float* p, float4 a) {
    asm volatile("red.global.add.v4.f32 [%0], {%1, %2, %3, %4};"
                 :: "l"(p), "f"(a.x), "f"(a.y), "f"(a.z), "f"(a.w)
                 : "memory");
}
__device__ __forceinline__ void red_add_h2(uint32_t* p, float2 v) {
    __half2 h = __float22half2_rn(v);
    asm volatile("red.global.add.noftz.f16x2 [%0], %1;"
                 :: "l"(p), "r"(*reinterpret_cast<uint32_t*>(&h))
                 : "memory");
}

// ---- per-dtype feature row helpers (each d4-thread owns 4 features) ----
// Gathers return PACKED f32x2 pairs so the hot loop runs on FFMA2.
template <bool HALF>
__device__ __forceinline__ void ld_feat2x(const char* p, uint64_t& g01, uint64_t& g23) {
    if (HALF) {
        uint2 r = *reinterpret_cast<const uint2*>(p);
        float2 a = __half22float2(*reinterpret_cast<__half2*>(&r.x));
        float2 b = __half22float2(*reinterpret_cast<__half2*>(&r.y));
        g01 = pack2(a.x, a.y);
        g23 = pack2(b.x, b.y);
    } else {
        float4 g = *reinterpret_cast<const float4*>(p);
        g01 = pack2(g.x, g.y);
        g23 = pack2(g.z, g.w);
    }
}
template <bool HALF>
__device__ __forceinline__ void st_feat(char* p, float2 lo, float2 hi) {
    if (HALF) {
        uint2 u;
        __half2 h0 = __float22half2_rn(lo);
        __half2 h1 = __float22half2_rn(hi);
        u.x = *reinterpret_cast<uint32_t*>(&h0);
        u.y = *reinterpret_cast<uint32_t*>(&h1);
        *reinterpret_cast<uint2*>(p) = u;
    } else {
        *reinterpret_cast<float4*>(p) = make_float4(lo.x, lo.y, hi.x, hi.y);
    }
}
template <bool HALF>
__device__ __forceinline__ void red_feat(char* p, float2 lo, float2 hi) {
    if (HALF) {
        uint32_t* u = reinterpret_cast<uint32_t*>(p);
        red_add_h2(u + 0, lo);
        red_add_h2(u + 1, hi);
    } else {
        red_add_v4(reinterpret_cast<float*>(p), make_float4(lo.x, lo.y, hi.x, hi.y));
    }
}

// R9-proven sorted-row SpMM (16-thread groups, 2/warp): interior runs ->
// exclusive STG, boundary runs -> red.add into pre-zeroed dst. 8 gathers in
// flight; accumulation via packed FFMA2.
template <bool SRC_H, bool DST_H>
__global__ void __launch_bounds__(THREADS)
spmm_kernel(const char* __restrict__ src,
            const int*  __restrict__ erow,
            const int*  __restrict__ ecol,
            const float* __restrict__ eval,
            char*       __restrict__ dst,
            int n_edges) {
    constexpr int SRC_RB = SRC_H ? 128 : 256;
    constexpr int DST_RB = DST_H ? 128 : 256;
    constexpr int SRC_TB = SRC_H ? 8 : 16;
    constexpr int DST_TB = DST_H ? 8 : 16;

    __shared__ alignas(16) int   s_row[EPB];
    __shared__ alignas(16) int   s_off[EPB];   // col * SRC_RB
    __shared__ alignas(16) float s_val[EPB];

    const int base = blockIdx.x * EPB;
    const int tid  = threadIdx.x;

    // Vectorized staging; pad with last valid row, val = 0.
    {
        const int i = tid * 4;
        const int e = base + i;
        if (e + 3 < n_edges) {
            int4   r = *reinterpret_cast<const int4*>(erow + e);
            int4   c = *reinterpret_cast<const int4*>(ecol + e);
            float4 v = *reinterpret_cast<const float4*>(eval + e);
            c.x *= SRC_RB; c.y *= SRC_RB; c.z *= SRC_RB; c.w *= SRC_RB;
            *reinterpret_cast<int4*>(s_row + i)   = r;
            *reinterpret_cast<int4*>(s_off + i)   = c;
            *reinterpret_cast<float4*>(s_val + i) = v;
        } else {
            #pragma unroll
            for (int k = 0; k < 4; k++) {
                int ee   = e + k;
                int esrc = min(ee, n_edges - 1);
                int in   = (ee < n_edges);
                s_row[i + k] = erow[esrc];
                s_off[i + k] = in ? ecol[esrc] * SRC_RB : 0;
                s_val[i + k] = in ? eval[esrc] : 0.f;
            }
        }
    }
    __syncthreads();

    const int d4  = tid & 15;
    const int sub = tid >> 4;
    const int off = sub * EPS;
    const char* sp = src + d4 * SRC_TB;
    char*       dp = dst + d4 * DST_TB;

    int      cur       = s_row[off];
    int      run_start = 0;
    uint64_t a01       = 0, a23 = 0;           // packed f32x2 accumulators

    for (int ib = 0; ib < EPS; ib += 8) {
        const int4   ra = *reinterpret_cast<const int4*>(s_row + off + ib);
        const int4   rb = *reinterpret_cast<const int4*>(s_row + off + ib + 4);
        const int4   ca = *reinterpret_cast<const int4*>(s_off + off + ib);
        const int4   cb = *reinterpret_cast<const int4*>(s_off + off + ib + 4);
        const float4 va = *reinterpret_cast<const float4*>(s_val + off + ib);
        const float4 vb = *reinterpret_cast<const float4*>(s_val + off + ib + 4);

        // 8 gathers in flight (MLP = 8), values pre-packed as f32x2
        uint64_t g0a, g0b, g1a, g1b, g2a, g2b, g3a, g3b;
        uint64_t g4a, g4b, g5a, g5b, g6a, g6b, g7a, g7b;
        ld_feat2x<SRC_H>(sp + ca.x, g0a, g0b);
        ld_feat2x<SRC_H>(sp + ca.y, g1a, g1b);
        ld_feat2x<SRC_H>(sp + ca.z, g2a, g2b);
        ld_feat2x<SRC_H>(sp + ca.w, g3a, g3b);
        ld_feat2x<SRC_H>(sp + cb.x, g4a, g4b);
        ld_feat2x<SRC_H>(sp + cb.y, g5a, g5b);
        ld_feat2x<SRC_H>(sp + cb.z, g6a, g6b);
        ld_feat2x<SRC_H>(sp + cb.w, g7a, g7b);

        #define STEP(R, V, GA, GB, IDX)                                      \
        do {                                                                 \
            if ((R) != cur) {                                                \
                char* p = dp + (size_t)cur * DST_RB;                         \
                float2 lo = unpack2(a01), hi = unpack2(a23);                 \
                if (run_start > 0) {                                         \
                    st_feat<DST_H>(p, lo, hi);     /* exclusive interior */  \
                } else {                                                     \
                    red_feat<DST_H>(p, lo, hi);    /* boundary */            \
                }                                                            \
                a01 = 0; a23 = 0;                                            \
                cur = (R);                                                   \
                run_start = (IDX);                                           \
            }                                                                \
            {                                                                \
                uint64_t vv = pack2((V), (V));                               \
                fma2(a01, (GA), vv);                                         \
                fma2(a23, (GB), vv);                                         \
            }                                                                \
        } while (0)

        STEP(ra.x, va.x, g0a, g0b, ib + 0);
        STEP(ra.y, va.y, g1a, g1b, ib + 1);
        STEP(ra.z, va.z, g2a, g2b, ib + 2);
        STEP(ra.w, va.w, g3a, g3b, ib + 3);
        STEP(rb.x, vb.x, g4a, g4b, ib + 4);
        STEP(rb.y, vb.y, g5a, g5b, ib + 5);
        STEP(rb.z, vb.z, g6a, g6b, ib + 6);
        STEP(rb.w, vb.w, g7a, g7b, ib + 7);
        #undef STEP
    }

    // Final run may continue into the next group -> always atomic.
    red_feat<DST_H>(dp + (size_t)cur * DST_RB, unpack2(a01), unpack2(a23));
}

extern "C" void kernel_launch(void* const* d_in, const int* in_sizes, int n_in,
                              void* d_out, int out_size) {
    const char*  x    = (const char*) d_in[0];
    const int*   erow = (const int*)  d_in[1];
    const int*   ecol = (const int*)  d_in[2];
    const float* eval = (const float*)d_in[3];
    char*        out  = (char*)d_out;

    const int n_edges = in_sizes[1];
    const int n_rows  = out_size / D_FEAT;
    const int n_elems = n_rows * D_FEAT;

    void* tmp_sym = nullptr;
    cudaGetSymbolAddress(&tmp_sym, g_tmp);
    char* tmp = (char*)tmp_sym;

    const int sgrid = (n_edges + EPB - 1) / EPB;

    // Host-side resources for the fork/join (no device memory involved).
    static cudaStream_t side = nullptr;
    static cudaEvent_t  ev_fork = nullptr, ev_join = nullptr;
    if (!side) {
        cudaStreamCreateWithFlags(&side, cudaStreamNonBlocking);
        cudaEventCreateWithFlags(&ev_fork, cudaEventDisableTiming);
        cudaEventCreateWithFlags(&ev_join, cudaEventDisableTiming);
    }

    // Critical path: zero tmp (needed by hop 1's boundary red.adds).
    cudaMemsetAsync(tmp, 0, (size_t)n_elems * 2);

    // Fork: zero out on the side stream, overlapping hop 1.
    cudaEventRecord(ev_fork, 0);
    cudaStreamWaitEvent(side, ev_fork, 0);
    cudaMemsetAsync(out, 0, (size_t)n_elems * 4, side);
    cudaEventRecord(ev_join, side);

    // Hop 1: tmp(fp16) = A @ x(fp32)   (overlaps memset(out))
    spmm_kernel<false, true><<<sgrid, THREADS>>>(x, erow, ecol, eval, tmp, n_edges);

    // Join: out must be zeroed before hop 2's red.adds.
    cudaStreamWaitEvent(0, ev_join, 0);

    // Hop 2: out(fp32) = A @ tmp(fp16)
    spmm_kernel<true, false><<<sgrid, THREADS>>>(tmp, erow, ecol, eval, out, n_edges);
}